// round 4
// baseline (speedup 1.0000x reference)
#include <cuda_runtime.h>

#define BATCH 2
#define CIN 3
#define C2 64
#define H 512
#define W 512
#define MS 504
#define S1 168
#define S2 56
#define S3 19
#define S4 7
#define S5 3

// ---------------- scratch (static device memory; no allocations) ----------------
__device__ unsigned char g_bins[BATCH*CIN*H*W];
__device__ unsigned char g_mode[BATCH*CIN*MS*MS];
__device__ float g_d1[BATCH*C2*S1*S1];
__device__ float g_d2[BATCH*C2*S2*S2];
__device__ float g_d3[BATCH*C2*S3*S3];
__device__ float g_d4[BATCH*C2*S4*S4];
__device__ float g_d5[BATCH*C2*S5*S5];
__device__ float g_bufA[BATCH*C2*H*W];

// ---------------- helpers ----------------
__device__ __forceinline__ float leaky(float x)    { return x >= 0.f ? x : 0.01f*x; }
__device__ __forceinline__ float maxleaky(float x) { return x <= 0.1f ? x : 0.1f + 0.01f*(x - 0.1f); }
__device__ __forceinline__ float minleaky(float x) { return x >= 0.1f ? x : 0.1f + 0.01f*(x - 0.1f); }

typedef unsigned long long ull;
__device__ __forceinline__ ull pk2(float a, float b) {
    ull r; asm("mov.b64 %0, {%1, %2};" : "=l"(r) : "f"(a), "f"(b)); return r;
}
__device__ __forceinline__ ull fma2(ull a, ull b, ull c) {
    ull d; asm("fma.rn.f32x2 %0, %1, %2, %3;" : "=l"(d) : "l"(a), "l"(b), "l"(c)); return d;
}
__device__ __forceinline__ float2 upk2(ull v) {
    float2 f; asm("mov.b64 {%0, %1}, %2;" : "=f"(f.x), "=f"(f.y) : "l"(v)); return f;
}

// ---------------- 1) quantize to bins (float4 vectorized) ----------------
__global__ void quant_kernel(const float* __restrict__ x) {
    int i = blockIdx.x*blockDim.x + threadIdx.x;
    const int N4 = BATCH*CIN*H*W/4;
    if (i >= N4) return;
    float4 v = ((const float4*)x)[i];
    uchar4 o;
    float r;
    r = fminf(fmaxf(rintf(v.x*255.0f*0.0625f), 0.f), 16.f); o.x = (unsigned char)r;
    r = fminf(fmaxf(rintf(v.y*255.0f*0.0625f), 0.f), 16.f); o.y = (unsigned char)r;
    r = fminf(fmaxf(rintf(v.z*255.0f*0.0625f), 0.f), 16.f); o.z = (unsigned char)r;
    r = fminf(fmaxf(rintf(v.w*255.0f*0.0625f), 0.f), 16.f); o.w = (unsigned char)r;
    ((uchar4*)g_bins)[i] = o;
}

// ---------------- 2) mode pool 11x11 (pad=1), sliding packed histogram ----------------
__device__ __forceinline__ void hist_add(ull &h0, ull &h1, int &h16, int bin) {
    if (bin < 8)       h0 += 1ull << (bin*8);
    else if (bin < 16) h1 += 1ull << ((bin-8)*8);
    else               h16++;
}
__device__ __forceinline__ void hist_sub(ull &h0, ull &h1, int &h16, int bin) {
    if (bin < 8)       h0 -= 1ull << (bin*8);
    else if (bin < 16) h1 -= 1ull << ((bin-8)*8);
    else               h16--;
}
template<bool INTERIOR>
__device__ __forceinline__ void row_update(const unsigned char* __restrict__ bp, int yy, int x,
                                           ull &h0, ull &h1, int &h16, bool add) {
    if (yy < 0 || yy >= H) { if (add) h0 += 11ull; else h0 -= 11ull; return; }
    const unsigned char* rp = bp + yy*W;
    #pragma unroll
    for (int j = 0; j < 11; j++) {
        int xx = x - 1 + j;
        int bin;
        if (INTERIOR) bin = (int)rp[xx];
        else          bin = (xx >= 0 && xx < W) ? (int)rp[xx] : 0;
        if (add) hist_add(h0, h1, h16, bin); else hist_sub(h0, h1, h16, bin);
    }
}

#define MODE_CHUNK 14
template<bool INTERIOR>
__device__ __forceinline__ void mode_body(int x, int bc, int ystart) {
    int yend = ystart + MODE_CHUNK;
    const unsigned char* bp = g_bins + (size_t)bc*H*W;
    unsigned char* mp = g_mode + (size_t)bc*MS*MS;

    ull h0 = 0, h1 = 0; int h16 = 0;
    for (int yy = ystart-1; yy <= ystart+9; yy++) row_update<INTERIOR>(bp, yy, x, h0, h1, h16, true);

    for (int y = ystart; y < yend; y++) {
        int best = (int)(h0 & 0xffull); int bb = 0;
        #pragma unroll
        for (int bnum = 1; bnum < 8; bnum++) {
            int cn = (int)((h0 >> (bnum*8)) & 0xffull);
            if (cn > best) { best = cn; bb = bnum; }
        }
        #pragma unroll
        for (int bnum = 0; bnum < 8; bnum++) {
            int cn = (int)((h1 >> (bnum*8)) & 0xffull);
            if (cn > best) { best = cn; bb = bnum + 8; }
        }
        if (h16 > best) bb = 16;
        mp[y*MS + x] = (unsigned char)bb;
        if (y + 1 < yend) {
            row_update<INTERIOR>(bp, y-1,  x, h0, h1, h16, false);
            row_update<INTERIOR>(bp, y+10, x, h0, h1, h16, true);
        }
    }
}

__global__ void mode_kernel() {
    int x = blockIdx.x*blockDim.x + threadIdx.x;
    if (x >= MS) return;
    int bc = blockIdx.z;
    int ystart = blockIdx.y * MODE_CHUNK;
    if (x >= 1 && x <= 502) mode_body<true>(x, bc, ystart);
    else                    mode_body<false>(x, bc, ystart);
}

// ---------------- 3) fused prepare (1x1 convs + clamps) + downgrade level 1 ----------------
__global__ void d1_kernel(const float* __restrict__ w1, const float* __restrict__ b1,
                          const float* __restrict__ w2, const float* __restrict__ b2,
                          const float* __restrict__ dk, const float* __restrict__ dbp) {
    int tile = blockIdx.x;            // 11x11 tiles of 16
    int g = blockIdx.y;               // group 0..31 -> channels 2g, 2g+1
    int b = blockIdx.z;
    int ty = (tile/11)*16 + (threadIdx.x >> 4);
    int tx = (tile%11)*16 + (threadIdx.x & 15);
    if (ty >= S1 || tx >= S1) return;

    int o0 = 2*g, o1 = 2*g + 1;
    float w1a0 = __ldg(w1 + o0*3 + 0), w1a1 = __ldg(w1 + o0*3 + 1), w1a2 = __ldg(w1 + o0*3 + 2);
    float w1b0 = __ldg(w1 + o1*3 + 0), w1b1 = __ldg(w1 + o1*3 + 1), w1b2 = __ldg(w1 + o1*3 + 2);
    float b1a = __ldg(b1 + o0), b1b = __ldg(b1 + o1);
    float w2a0 = __ldg(w2 + o0*2 + 0), w2a1 = __ldg(w2 + o0*2 + 1), b2a = __ldg(b2 + o0);
    float w2b0 = __ldg(w2 + o1*2 + 0), w2b1 = __ldg(w2 + o1*2 + 1), b2b = __ldg(b2 + o1);
    float kk[9];
    #pragma unroll
    for (int i = 0; i < 9; i++) kk[i] = __ldg(dk + i);
    float db = __ldg(dbp);

    const unsigned char* m0 = g_mode + (size_t)(b*CIN + 0)*MS*MS;
    const unsigned char* m1 = g_mode + (size_t)(b*CIN + 1)*MS*MS;
    const unsigned char* m2 = g_mode + (size_t)(b*CIN + 2)*MS*MS;

    float acc0 = db, acc1 = db;
    #pragma unroll
    for (int i = 0; i < 3; i++) {
        #pragma unroll
        for (int j = 0; j < 3; j++) {
            int yy = 3*ty - 1 + i, xx = 3*tx - 1 + j;
            float d0a = 0.f, d0b = 0.f;
            if (yy >= 0 && yy < MS && xx >= 0 && xx < MS) {
                int off = yy*MS + xx;
                float v0 = (float)m0[off]*0.0625f;
                float v1 = (float)m1[off]*0.0625f;
                float v2 = (float)m2[off]*0.0625f;
                float ha = maxleaky(w1a0*v0 + w1a1*v1 + w1a2*v2 + b1a);
                float hb = maxleaky(w1b0*v0 + w1b1*v1 + w1b2*v2 + b1b);
                d0a = minleaky(w2a0*ha + w2a1*hb + b2a);
                d0b = minleaky(w2b0*ha + w2b1*hb + b2b);
            }
            acc0 += kk[i*3+j]*d0a;
            acc1 += kk[i*3+j]*d0b;
        }
    }
    g_d1[((size_t)(b*C2 + o0)*S1 + ty)*S1 + tx] = leaky(acc0);
    g_d1[((size_t)(b*C2 + o1)*S1 + ty)*S1 + tx] = leaky(acc1);
}

// ---------------- 4) downgrade level 2 ----------------
__global__ void down2_kernel(const float* __restrict__ dk, const float* __restrict__ dbp) {
    int idx = blockIdx.x*blockDim.x + threadIdx.x;
    const int total = BATCH*C2*S2*S2;
    if (idx >= total) return;
    int x = idx % S2;
    int y = (idx/S2) % S2;
    int bc = idx/(S2*S2);
    const float* ip = g_d1 + (size_t)bc*S1*S1;
    float acc = __ldg(dbp);
    #pragma unroll
    for (int i = 0; i < 3; i++) {
        #pragma unroll
        for (int j = 0; j < 3; j++) {
            int yy = 3*y - 1 + i, xx = 3*x - 1 + j;
            if (yy >= 0 && yy < S1 && xx >= 0 && xx < S1)
                acc += __ldg(dk + i*3 + j) * ip[yy*S1 + xx];
        }
    }
    g_d2[idx] = leaky(acc);
}

// ---------------- 4b) downgrade levels 3,4,5 fused ----------------
template<int IS, int OS>
__device__ __forceinline__ void down_step(const float* __restrict__ in, float* __restrict__ out,
                                          const float* kk, float db, int tid, int nthr) {
    for (int i = tid; i < OS*OS; i += nthr) {
        int x = i % OS, y = i / OS;
        float acc = db;
        #pragma unroll
        for (int ii = 0; ii < 3; ii++) {
            #pragma unroll
            for (int jj = 0; jj < 3; jj++) {
                int yy = 3*y - 1 + ii, xx = 3*x - 1 + jj;
                if (yy >= 0 && yy < IS && xx >= 0 && xx < IS)
                    acc += kk[ii*3+jj] * in[yy*IS + xx];
            }
        }
        out[i] = leaky(acc);
    }
}

__global__ void down345_kernel(const float* __restrict__ dk, const float* __restrict__ dbp) {
    int bc = blockIdx.x;
    int tid = threadIdx.x;
    float kk[9];
    #pragma unroll
    for (int i = 0; i < 9; i++) kk[i] = __ldg(dk + i);
    float db = __ldg(dbp);
    down_step<S2, S3>(g_d2 + (size_t)bc*S2*S2, g_d3 + (size_t)bc*S3*S3, kk, db, tid, blockDim.x);
    __syncthreads();
    down_step<S3, S4>(g_d3 + (size_t)bc*S3*S3, g_d4 + (size_t)bc*S4*S4, kk, db, tid, blockDim.x);
    __syncthreads();
    down_step<S4, S5>(g_d4 + (size_t)bc*S4*S4, g_d5 + (size_t)bc*S5*S5, kk, db, tid, blockDim.x);
}

// ---------------- 5) score: 5 levels of resize -> conv5 -> bn -> leaky, accumulated ----------------
// Tile 128 wide x 32 tall, 256 threads. Thread: 4 contiguous rows x 4 contiguous cols.
#define ZST 132

struct ScoreShared {
    float zs[36*ZST];
    float k5[25];
    int   ro0[36]; int ro1[36]; float rw[36]; float rv[36];
    int   co0[132]; int co1[132]; float cw[132]; float cv[132];
};

template<int S>
__device__ __forceinline__ void score_level(ScoreShared* sh, const float* __restrict__ dch,
                                            int ty0, int tx0, int tid, const ull* kp,
                                            float iscale, float ibias, float interpb,
                                            float sacc[4][4]) {
    const float scale = (float)S / 512.0f;
    // row params (36) and col params (132)
    if (tid < 36) {
        int u = ty0 - 2 + tid;
        float fy = ((float)u + 0.5f)*scale - 0.5f;
        float fyl = floorf(fy);
        int y0i = (int)fyl;
        int ya = min(max(y0i,     0), S-1);
        int yb = min(max(y0i + 1, 0), S-1);
        sh->ro0[tid] = ya*S;
        sh->ro1[tid] = yb*S;
        sh->rw[tid]  = fy - fyl;
        sh->rv[tid]  = ((unsigned)u < (unsigned)H) ? 1.0f : 0.0f;
    } else if (tid >= 64 && tid < 196) {
        int cc = tid - 64;
        int v = tx0 - 2 + cc;
        float fx = ((float)v + 0.5f)*scale - 0.5f;
        float fxl = floorf(fx);
        int x0i = (int)fxl;
        int xa = min(max(x0i,     0), S-1);
        int xb = min(max(x0i + 1, 0), S-1);
        sh->co0[cc] = xa;
        sh->co1[cc] = xb;
        sh->cw[cc]  = fx - fxl;
        sh->cv[cc]  = ((unsigned)v < (unsigned)W) ? 1.0f : 0.0f;
    }
    __syncthreads();
    // bilinear fill: 36 x 132
    for (int i = tid; i < 36*132; i += 256) {
        int iu = i / 132;
        int iv = i - iu*132;
        int r0 = sh->ro0[iu], r1 = sh->ro1[iu];
        int c0 = sh->co0[iv], c1 = sh->co1[iv];
        float ay = sh->rw[iu], ax = sh->cw[iv];
        float m = sh->rv[iu] * sh->cv[iv];
        float v00 = __ldg(dch + r0 + c0);
        float v01 = __ldg(dch + r0 + c1);
        float v10 = __ldg(dch + r1 + c0);
        float v11 = __ldg(dch + r1 + c1);
        float top = v00 + ax*(v01 - v00);
        float bot = v10 + ax*(v11 - v10);
        sh->zs[iu*ZST + iv] = m*(top + ay*(bot - top));
    }
    __syncthreads();
    // conv 5x5: thread g=tid>>5 rows 4g..4g+3, p=tid&31 cols 4p..4p+3
    int g = tid >> 5;
    int p = tid & 31;
    ull A01[4], A23[4];
    ull z = pk2(0.f, 0.f);
    #pragma unroll
    for (int r = 0; r < 4; r++) { A01[r] = z; A23[r] = z; }
    #pragma unroll
    for (int iy = 0; iy < 8; iy++) {
        const float* rp = &sh->zs[(4*g + iy)*ZST + 4*p];
        float4 q0 = *(const float4*)rp;
        float4 q1 = *(const float4*)(rp + 4);
        ull w0 = pk2(q0.x, q0.y), w1 = pk2(q0.y, q0.z), w2 = pk2(q0.z, q0.w),
            w3 = pk2(q0.w, q1.x), w4 = pk2(q1.x, q1.y), w5 = pk2(q1.y, q1.z),
            w6 = pk2(q1.z, q1.w);
        #pragma unroll
        for (int r = 0; r < 4; r++) {
            int dy = iy - r;
            if (dy < 0 || dy > 4) continue;
            const int kb = dy*5;
            A01[r] = fma2(kp[kb+0], w0, A01[r]); A23[r] = fma2(kp[kb+0], w2, A23[r]);
            A01[r] = fma2(kp[kb+1], w1, A01[r]); A23[r] = fma2(kp[kb+1], w3, A23[r]);
            A01[r] = fma2(kp[kb+2], w2, A01[r]); A23[r] = fma2(kp[kb+2], w4, A23[r]);
            A01[r] = fma2(kp[kb+3], w3, A01[r]); A23[r] = fma2(kp[kb+3], w5, A23[r]);
            A01[r] = fma2(kp[kb+4], w4, A01[r]); A23[r] = fma2(kp[kb+4], w6, A23[r]);
        }
    }
    #pragma unroll
    for (int r = 0; r < 4; r++) {
        float2 a01 = upk2(A01[r]);
        float2 a23 = upk2(A23[r]);
        float av[4] = {a01.x, a01.y, a23.x, a23.y};
        #pragma unroll
        for (int cc = 0; cc < 4; cc++) {
            float t = (av[cc] + interpb)*iscale + ibias;
            sacc[r][cc] += (t >= 0.f) ? t : 0.01f*t;
        }
    }
    __syncthreads();
}

__global__ void __launch_bounds__(256) score_kernel(
                             const float* __restrict__ ik, const float* __restrict__ ibp,
                             const float* __restrict__ ig, const float* __restrict__ ibeta,
                             const float* __restrict__ imean, const float* __restrict__ ivar) {
    __shared__ ScoreShared sh;
    int tile = blockIdx.x;            // 4 x-tiles x 16 y-tiles
    int c = blockIdx.y, b = blockIdx.z;
    int tx0 = (tile & 3)*128, ty0 = (tile >> 2)*32;
    int tid = threadIdx.x;
    if (tid < 25) sh.k5[tid] = __ldg(ik + tid);
    __syncthreads();

    ull kp[25];
    #pragma unroll
    for (int i = 0; i < 25; i++) { float kv = sh.k5[i]; kp[i] = pk2(kv, kv); }

    float iscale = __ldg(ig + c) * rsqrtf(__ldg(ivar + c) + 1e-5f);
    float ibias  = __ldg(ibeta + c) - __ldg(imean + c)*iscale;
    float interpb = __ldg(ibp);
    float sacc[4][4] = {{0.f,0.f,0.f,0.f},{0.f,0.f,0.f,0.f},{0.f,0.f,0.f,0.f},{0.f,0.f,0.f,0.f}};

    size_t choff = (size_t)(b*C2 + c);
    score_level<S1>(&sh, g_d1 + choff*S1*S1, ty0, tx0, tid, kp, iscale, ibias, interpb, sacc);
    score_level<S2>(&sh, g_d2 + choff*S2*S2, ty0, tx0, tid, kp, iscale, ibias, interpb, sacc);
    score_level<S3>(&sh, g_d3 + choff*S3*S3, ty0, tx0, tid, kp, iscale, ibias, interpb, sacc);
    score_level<S4>(&sh, g_d4 + choff*S4*S4, ty0, tx0, tid, kp, iscale, ibias, interpb, sacc);
    score_level<S5>(&sh, g_d5 + choff*S5*S5, ty0, tx0, tid, kp, iscale, ibias, interpb, sacc);

    int g = tid >> 5, p = tid & 31;
    float* op = g_bufA + choff*H*W;
    #pragma unroll
    for (int r = 0; r < 4; r++) {
        float4 o4; o4.x = sacc[r][0]; o4.y = sacc[r][1]; o4.z = sacc[r][2]; o4.w = sacc[r][3];
        *(float4*)(op + (size_t)(ty0 + 4*g + r)*W + tx0 + 4*p) = o4;
    }
}

// ---------------- 6) ft x3 fused ----------------
// Per stage, with raw-input box sum (zeros outside image):
//   out = alpha*cen - beta*box_in + Bc*(1+w) - (w*Bc/121)*cnt(y,x)
// cnt = cy(gy)*cx(gx) = #in-image pixels of the 11x11 window (SAME zero-pad happens
// in the post-affine domain in the reference; the cnt term accounts for that).
#define FT_EXT 62
#define FT_AST 64
#define FT_HST 53
__global__ void __launch_bounds__(256) ft3_kernel(float* __restrict__ dout,
                          const float* __restrict__ fg, const float* __restrict__ fb,
                          const float* __restrict__ fm, const float* __restrict__ fv,
                          const float* __restrict__ fkp, const float* __restrict__ fbp,
                          const float* __restrict__ ew) {
    __shared__ float sA[FT_EXT*FT_AST];
    __shared__ float sH[FT_EXT*FT_HST];
    int tile = blockIdx.x, c = blockIdx.y, b = blockIdx.z;
    int y0 = (tile >> 4)*32, x0 = (tile & 15)*32;
    int tid = threadIdx.x;

    float sc = __ldg(fg + c) * rsqrtf(__ldg(fv + c) + 1e-5f);
    float k  = __ldg(fkp);
    float A  = sc*k;
    float Bc = (__ldg(fb + c) - __ldg(fm + c)*sc)*k + __ldg(fbp);
    float w  = __ldg(ew + c);
    float alpha  = A*(1.0f + w);
    float beta   = A*w*(1.0f/121.0f);
    float gamma1 = Bc*(1.0f + w);
    float gamma2 = w*Bc*(1.0f/121.0f);

    const float* ip = g_bufA + (size_t)(b*C2 + c)*H*W;
    // fill 62x62 ext (zero outside image)
    for (int i = tid; i < FT_EXT*FT_EXT; i += 256) {
        int r = i / FT_EXT;
        int cc = i - r*FT_EXT;
        int gy = y0 - 15 + r, gx = x0 - 15 + cc;
        float v = 0.f;
        if ((unsigned)gy < (unsigned)H && (unsigned)gx < (unsigned)W)
            v = ip[(size_t)gy*W + gx];
        sA[r*FT_AST + cc] = v;
    }
    __syncthreads();

    #pragma unroll
    for (int s = 0; s < 3; s++) {
        const int o = 5*s;
        const int E = FT_EXT - 10*s;      // 62, 52, 42
        const int outw = E - 10;          // 52, 42, 32
        // horizontal 11-sums: units = E rows x 4 segments
        {
            int q = (outw + 3) >> 2;
            for (int u = tid; u < E*4; u += 256) {
                int r = u >> 2, seg = u & 3;
                int c0 = seg*q, c1 = min(c0 + q, outw);
                if (c0 >= c1) continue;
                const float* rp = &sA[(o + r)*FT_AST + o];
                float ssum = 0.f;
                #pragma unroll
                for (int j = 0; j < 11; j++) ssum += rp[c0 + j];
                float* hp = &sH[r*FT_HST];
                hp[c0] = ssum;
                for (int cc = c0 + 1; cc < c1; cc++) {
                    ssum += rp[cc + 10] - rp[cc - 1];
                    hp[cc] = ssum;
                }
            }
        }
        __syncthreads();
        // vertical 11-sums + combine (with border-count correction)
        {
            const int segs = (s == 2) ? 8 : 4;
            const int rpseg = (outw + segs - 1)/segs;
            for (int u = tid; u < outw*segs; u += 256) {
                int x = u % outw;
                int seg = u / outw;
                int r0 = seg*rpseg, r1 = min(r0 + rpseg, outw);
                if (r0 >= r1) continue;
                int gx = x0 - 10 + o + x;   // global x of output pixel
                int cx = 11 - max(0, 5 - gx) - max(0, gx - (W - 6));
                float bsum = 0.f;
                #pragma unroll
                for (int j = 0; j < 11; j++) bsum += sH[(r0 + j)*FT_HST + x];
                for (int r = r0; r < r1; r++) {
                    if (r > r0) bsum += sH[(r + 10)*FT_HST + x] - sH[(r - 1)*FT_HST + x];
                    int ey = o + r + 5, ex = o + x + 5;
                    int gy = y0 - 10 + o + r;
                    float cen = sA[ey*FT_AST + ex];
                    if (s == 2) {
                        // gy,gx always inside image here
                        int cy = 11 - max(0, 5 - gy) - max(0, gy - (H - 6));
                        float val = alpha*cen - beta*bsum + gamma1 - gamma2*(float)(cy*cx);
                        dout[((size_t)(b*C2 + c)*H + (y0 + r))*W + (x0 + x)] = val;
                    } else {
                        bool inim = ((unsigned)gy < (unsigned)H) && ((unsigned)gx < (unsigned)W);
                        int cy = 11 - max(0, 5 - gy) - max(0, gy - (H - 6));
                        float val = alpha*cen - beta*bsum + gamma1 - gamma2*(float)(cy*cx);
                        sA[ey*FT_AST + ex] = inim ? val : 0.f;
                    }
                }
            }
        }
        __syncthreads();
    }
}

// ---------------- launch ----------------
extern "C" void kernel_launch(void* const* d_in, const int* in_sizes, int n_in,
                              void* d_out, int out_size) {
    const float* x        = (const float*)d_in[0];
    const float* w1       = (const float*)d_in[1];
    const float* b1       = (const float*)d_in[2];
    const float* w2       = (const float*)d_in[3];
    const float* b2       = (const float*)d_in[4];
    const float* down_k   = (const float*)d_in[5];
    const float* down_b   = (const float*)d_in[6];
    const float* ft_gamma = (const float*)d_in[7];
    const float* ft_beta  = (const float*)d_in[8];
    const float* ft_mean  = (const float*)d_in[9];
    const float* ft_var   = (const float*)d_in[10];
    const float* ft_k     = (const float*)d_in[11];
    const float* ft_b     = (const float*)d_in[12];
    const float* emph_w   = (const float*)d_in[13];
    const float* interp_k = (const float*)d_in[14];
    const float* interp_b = (const float*)d_in[15];
    const float* i_gamma  = (const float*)d_in[16];
    const float* i_beta   = (const float*)d_in[17];
    const float* i_mean   = (const float*)d_in[18];
    const float* i_var    = (const float*)d_in[19];
    float* out = (float*)d_out;

    quant_kernel<<<(BATCH*CIN*H*W/4 + 255)/256, 256>>>(x);

    dim3 mg((MS + 127)/128, MS/MODE_CHUNK, BATCH*CIN);
    mode_kernel<<<mg, 128>>>();

    dim3 g1(121, C2/2, BATCH);
    d1_kernel<<<g1, 256>>>(w1, b1, w2, b2, down_k, down_b);

    down2_kernel<<<(BATCH*C2*S2*S2 + 255)/256, 256>>>(down_k, down_b);
    down345_kernel<<<BATCH*C2, 384>>>(down_k, down_b);

    dim3 gs(64, C2, BATCH);
    score_kernel<<<gs, 256>>>(interp_k, interp_b, i_gamma, i_beta, i_mean, i_var);

    dim3 gf(256, C2, BATCH);
    ft3_kernel<<<gf, 256>>>(out, ft_gamma, ft_beta, ft_mean, ft_var, ft_k, ft_b, emph_w);
}